// round 1
// baseline (speedup 1.0000x reference)
#include <cuda_runtime.h>

#define DD 64
#define KK 512

// Packed fp32x2 FMA (SASS FFMA2) — only reachable via PTX, 2 MACs/instr.
__device__ __forceinline__ void fma2(unsigned long long &d,
                                     unsigned long long a,
                                     unsigned long long b,
                                     unsigned long long c) {
    asm("fma.rn.f32x2 %0, %1, %2, %3;" : "=l"(d) : "l"(a), "l"(b), "l"(c));
}

__device__ __forceinline__ void add2(unsigned long long &d,
                                     unsigned long long a,
                                     unsigned long long b) {
    asm("add.rn.f32x2 %0, %1, %2;" : "=l"(d) : "l"(a), "l"(b));
}

__device__ __forceinline__ float2 unpack2(unsigned long long v) {
    float2 r;
    asm("mov.b64 {%0, %1}, %2;" : "=f"(r.x), "=f"(r.y) : "l"(v));
    return r;
}

__global__ __launch_bounds__(512)
void vq_argmin_kernel(const float* __restrict__ x,
                      const float* __restrict__ emb,
                      float* __restrict__ out,
                      int N, int write_idx) {
    extern __shared__ float smem[];           // [KK*DD] codes, then [KK] half-sq-norms
    float* se = smem;
    float* sc = smem + KK * DD;

    const int tid = threadIdx.x;

    // Stage codebook into shared memory (coalesced float4).
    {
        const float4* g4 = (const float4*)emb;
        float4* s4 = (float4*)se;
        #pragma unroll 4
        for (int i = tid; i < KK * DD / 4; i += blockDim.x) s4[i] = g4[i];
    }
    __syncthreads();

    // Per-block: 0.5*||e_k||^2 (cheap, 512 rows).
    for (int k = tid; k < KK; k += blockDim.x) {
        const float4* r = (const float4*)(se + k * DD);
        float s = 0.f;
        #pragma unroll
        for (int i = 0; i < DD / 4; i++) {
            float4 v = r[i];
            s += v.x * v.x + v.y * v.y + v.z * v.z + v.w * v.w;
        }
        sc[k] = 0.5f * s;
    }
    __syncthreads();

    const int row = blockIdx.x * blockDim.x + tid;
    if (row >= N) return;

    // Own x-row in registers, packed as 32 f32x2.
    unsigned long long xr[DD / 2];
    {
        const ulonglong2* xp = (const ulonglong2*)(x + (size_t)row * DD);
        #pragma unroll
        for (int i = 0; i < DD / 4; i++) {
            ulonglong2 v = xp[i];
            xr[2 * i]     = v.x;
            xr[2 * i + 1] = v.y;
        }
    }

    float best = -3.402823466e38f;
    int bidx = 0;

    #pragma unroll 2
    for (int k = 0; k < KK; ++k) {
        const ulonglong2* ep = (const ulonglong2*)(se + k * DD);
        // 4 independent packed accumulator chains for ILP.
        unsigned long long a0 = 0ull, a1 = 0ull, a2 = 0ull, a3 = 0ull;
        #pragma unroll
        for (int i = 0; i < 8; i++) {
            ulonglong2 e0 = ep[2 * i];        // LDS.128 broadcast (uniform addr)
            ulonglong2 e1 = ep[2 * i + 1];
            fma2(a0, xr[4 * i + 0], e0.x, a0);
            fma2(a1, xr[4 * i + 1], e0.y, a1);
            fma2(a2, xr[4 * i + 2], e1.x, a2);
            fma2(a3, xr[4 * i + 3], e1.y, a3);
        }
        add2(a0, a0, a1);
        add2(a2, a2, a3);
        float2 f0 = unpack2(a0);
        float2 f2 = unpack2(a2);
        float dot = (f0.x + f0.y) + (f2.x + f2.y);
        float t = dot - sc[k];                // maximize x.e - 0.5||e||^2
        if (t > best) { best = t; bidx = k; } // strict > keeps first index on ties
    }

    // Gather quantized row from smem.
    {
        const float4* sr = (const float4*)(se + bidx * DD);
        float4* orow = (float4*)(out + (size_t)row * DD);
        #pragma unroll
        for (int i = 0; i < DD / 4; i++) orow[i] = sr[i];
    }
    if (write_idx) {
        out[(size_t)N * DD + row] = (float)bidx;
    }
}

extern "C" void kernel_launch(void* const* d_in, const int* in_sizes, int n_in,
                              void* d_out, int out_size) {
    const float* x   = (const float*)d_in[0];   // flat_x  [N, 64]
    const float* emb = (const float*)d_in[1];   // codes   [512, 64]
    float* out = (float*)d_out;

    const int N = in_sizes[0] / DD;
    // If harness concatenates (quantized, indices) into one float buffer,
    // write indices as floats after the quantized block.
    const int write_idx = (out_size >= N * DD + N) ? 1 : 0;

    const size_t smem_bytes = (size_t)(KK * DD + KK) * sizeof(float);
    cudaFuncSetAttribute(vq_argmin_kernel,
                         cudaFuncAttributeMaxDynamicSharedMemorySize,
                         (int)smem_bytes);

    const int threads = 512;
    const int blocks = (N + threads - 1) / threads;
    vq_argmin_kernel<<<blocks, threads, smem_bytes>>>(x, emb, out, N, write_idx);
}

// round 2
// speedup vs baseline: 1.0615x; 1.0615x over previous
#include <cuda_runtime.h>

#define DD 64
#define KK 512
#define THREADS 256
#define ROWS_PER_BLOCK 512      // THREADS * 2
#define KCHUNK 256
#define XPITCH 68               // 64 + 4 pad floats -> conflict-free LDS.128

// Packed fp32x2 FMA (SASS FFMA2), 2 MACs/instr.
__device__ __forceinline__ void fma2(unsigned long long &d,
                                     unsigned long long a,
                                     unsigned long long b) {
    asm("fma.rn.f32x2 %0, %1, %2, %0;" : "+l"(d) : "l"(a), "l"(b));
}

__device__ __forceinline__ float2 unpack2(unsigned long long v) {
    float2 r;
    asm("mov.b64 {%0, %1}, %2;" : "=f"(r.x), "=f"(r.y) : "l"(v));
    return r;
}

__global__ __launch_bounds__(THREADS)
void vq_tiled_kernel(const float* __restrict__ x,
                     const float* __restrict__ emb,
                     float* __restrict__ out,
                     int N, int write_idx) {
    extern __shared__ float smem[];
    float* xs = smem;                                   // [ROWS_PER_BLOCK][XPITCH]
    float* cs = xs + ROWS_PER_BLOCK * XPITCH;           // [KCHUNK][DD]
    float* sc = cs + KCHUNK * DD;                       // [KCHUNK] 0.5*||e||^2

    const int tid = threadIdx.x;
    const int row0g = blockIdx.x * ROWS_PER_BLOCK;

    // ---- Stage x tile: 512 rows x 16 float4, coalesced; OOB rows -> 0 ----
    {
        const float4 z = make_float4(0.f, 0.f, 0.f, 0.f);
        for (int i = tid; i < ROWS_PER_BLOCK * (DD / 4); i += THREADS) {
            int r = i >> 4;              // local row
            int s = i & 15;              // float4 segment
            int g = row0g + r;
            float4 v = (g < N) ? ((const float4*)x)[(size_t)g * (DD / 4) + s] : z;
            *(float4*)(xs + r * XPITCH + s * 4) = v;
        }
    }

    // Two local rows per thread: tid and tid+256 (lane stride = 1 row -> conflict-free).
    const int lr0 = tid;
    const int lr1 = tid + THREADS;

    float best0 = -3.402823466e38f, best1 = -3.402823466e38f;
    int bi0 = 0, bi1 = 0;

    for (int chunk = 0; chunk < KK / KCHUNK; ++chunk) {
        const int kbase = chunk * KCHUNK;

        __syncthreads();   // xs staged (chunk 0) / previous chunk's cs reads done
        // ---- Stage code chunk ----
        for (int i = tid; i < KCHUNK * (DD / 4); i += THREADS) {
            ((float4*)cs)[i] = ((const float4*)emb)[(size_t)kbase * (DD / 4) + i];
        }
        __syncthreads();
        // ---- 0.5*||e||^2 per code ----
        for (int k = tid; k < KCHUNK; k += THREADS) {
            const float4* r = (const float4*)(cs + k * DD);
            float s = 0.f;
            #pragma unroll
            for (int i = 0; i < DD / 4; i++) {
                float4 v = r[i];
                s += v.x * v.x + v.y * v.y + v.z * v.z + v.w * v.w;
            }
            sc[k] = 0.5f * s;
        }
        __syncthreads();

        // ---- Main loop: tiles of 4 codes x 2 rows ----
        for (int kt = 0; kt < KCHUNK / 4; ++kt) {
            const float* c0 = cs + (kt * 4 + 0) * DD;
            const float* c1 = cs + (kt * 4 + 1) * DD;
            const float* c2 = cs + (kt * 4 + 2) * DD;
            const float* c3 = cs + (kt * 4 + 3) * DD;
            const float* xr0 = xs + lr0 * XPITCH;
            const float* xr1 = xs + lr1 * XPITCH;

            unsigned long long a00 = 0, a01 = 0, a02 = 0, a03 = 0;
            unsigned long long a10 = 0, a11 = 0, a12 = 0, a13 = 0;

            #pragma unroll
            for (int d = 0; d < DD; d += 4) {
                ulonglong2 xa = *(const ulonglong2*)(xr0 + d);
                ulonglong2 xb = *(const ulonglong2*)(xr1 + d);
                ulonglong2 e0 = *(const ulonglong2*)(c0 + d);   // broadcast
                ulonglong2 e1 = *(const ulonglong2*)(c1 + d);
                ulonglong2 e2 = *(const ulonglong2*)(c2 + d);
                ulonglong2 e3 = *(const ulonglong2*)(c3 + d);
                fma2(a00, xa.x, e0.x); fma2(a00, xa.y, e0.y);
                fma2(a01, xa.x, e1.x); fma2(a01, xa.y, e1.y);
                fma2(a02, xa.x, e2.x); fma2(a02, xa.y, e2.y);
                fma2(a03, xa.x, e3.x); fma2(a03, xa.y, e3.y);
                fma2(a10, xb.x, e0.x); fma2(a10, xb.y, e0.y);
                fma2(a11, xb.x, e1.x); fma2(a11, xb.y, e1.y);
                fma2(a12, xb.x, e2.x); fma2(a12, xb.y, e2.y);
                fma2(a13, xb.x, e3.x); fma2(a13, xb.y, e3.y);
            }

            const float n0 = sc[kt * 4 + 0];
            const float n1 = sc[kt * 4 + 1];
            const float n2 = sc[kt * 4 + 2];
            const float n3 = sc[kt * 4 + 3];
            const int kg = kbase + kt * 4;

            float2 f;
            // Row 0 — ascending k for first-tie (strict >) semantics.
            f = unpack2(a00); { float t = (f.x + f.y) - n0; if (t > best0) { best0 = t; bi0 = kg + 0; } }
            f = unpack2(a01); { float t = (f.x + f.y) - n1; if (t > best0) { best0 = t; bi0 = kg + 1; } }
            f = unpack2(a02); { float t = (f.x + f.y) - n2; if (t > best0) { best0 = t; bi0 = kg + 2; } }
            f = unpack2(a03); { float t = (f.x + f.y) - n3; if (t > best0) { best0 = t; bi0 = kg + 3; } }
            // Row 1
            f = unpack2(a10); { float t = (f.x + f.y) - n0; if (t > best1) { best1 = t; bi1 = kg + 0; } }
            f = unpack2(a11); { float t = (f.x + f.y) - n1; if (t > best1) { best1 = t; bi1 = kg + 1; } }
            f = unpack2(a12); { float t = (f.x + f.y) - n2; if (t > best1) { best1 = t; bi1 = kg + 2; } }
            f = unpack2(a13); { float t = (f.x + f.y) - n3; if (t > best1) { best1 = t; bi1 = kg + 3; } }
        }
    }

    // ---- Epilogue: gather best code rows from global (L2-resident 128 KB) ----
    const int g0 = row0g + lr0;
    const int g1 = row0g + lr1;
    if (g0 < N) {
        const float4* sr = (const float4*)(emb + (size_t)bi0 * DD);
        float4* orow = (float4*)(out + (size_t)g0 * DD);
        #pragma unroll
        for (int i = 0; i < DD / 4; i++) orow[i] = sr[i];
        if (write_idx) out[(size_t)N * DD + g0] = (float)bi0;
    }
    if (g1 < N) {
        const float4* sr = (const float4*)(emb + (size_t)bi1 * DD);
        float4* orow = (float4*)(out + (size_t)g1 * DD);
        #pragma unroll
        for (int i = 0; i < DD / 4; i++) orow[i] = sr[i];
        if (write_idx) out[(size_t)N * DD + g1] = (float)bi1;
    }
}

extern "C" void kernel_launch(void* const* d_in, const int* in_sizes, int n_in,
                              void* d_out, int out_size) {
    const float* x   = (const float*)d_in[0];   // flat_x  [N, 64]
    const float* emb = (const float*)d_in[1];   // codes   [512, 64]
    float* out = (float*)d_out;

    const int N = in_sizes[0] / DD;
    const int write_idx = (out_size >= N * DD + N) ? 1 : 0;

    const size_t smem_bytes =
        (size_t)(ROWS_PER_BLOCK * XPITCH + KCHUNK * DD + KCHUNK) * sizeof(float);
    cudaFuncSetAttribute(vq_tiled_kernel,
                         cudaFuncAttributeMaxDynamicSharedMemorySize,
                         (int)smem_bytes);

    const int blocks = (N + ROWS_PER_BLOCK - 1) / ROWS_PER_BLOCK;
    vq_tiled_kernel<<<blocks, THREADS, smem_bytes>>>(x, emb, out, N, write_idx);
}

// round 5
// speedup vs baseline: 2.8343x; 2.6701x over previous
#include <cuda_runtime.h>
#include <cuda_fp16.h>
#include <cstdint>

#define DD 64
#define KK 512
#define TILE_M 32
#define THREADS 256
#define PITCH 200          // halfs per row (conflict-free for ldmatrix)
#define PITCHB 400         // bytes per row

// smem layout (byte offsets)
#define SMB_B    0                       // 512 * 400 = 204800
#define SMB_A    204800                  // 32 * 400  = 12800
#define SMB_SC   217600                  // 512 floats = 2048
#define SMB_VAL  219648                  // float vals[32][4] = 512
#define SMB_IDX  220160                  // int   idxs[32][4] = 512
#define SMB_TOT  220672

__device__ __align__(16) __half g_B[KK * PITCH];
__device__ float g_sc[KK];

__device__ __forceinline__ uint32_t smem_u32(const void* p) {
    uint32_t a;
    asm("{ .reg .u64 t; cvta.to.shared.u64 t, %1; cvt.u32.u64 %0, t; }" : "=r"(a) : "l"(p));
    return a;
}

// split float4 -> fp16 hi (p1) and fp16 residual (p2), 4 halfs each
__device__ __forceinline__ void pack_h12(float4 v, uint64_t& p1, uint64_t& p2) {
    __half a1 = __float2half_rn(v.x), b1 = __float2half_rn(v.y);
    __half c1 = __float2half_rn(v.z), d1 = __float2half_rn(v.w);
    __half a2 = __float2half_rn(v.x - __half2float(a1));
    __half b2 = __float2half_rn(v.y - __half2float(b1));
    __half c2 = __float2half_rn(v.z - __half2float(c1));
    __half d2 = __float2half_rn(v.w - __half2float(d1));
    p1 = (uint64_t)__half_as_ushort(a1) | ((uint64_t)__half_as_ushort(b1) << 16)
       | ((uint64_t)__half_as_ushort(c1) << 32) | ((uint64_t)__half_as_ushort(d1) << 48);
    p2 = (uint64_t)__half_as_ushort(a2) | ((uint64_t)__half_as_ushort(b2) << 16)
       | ((uint64_t)__half_as_ushort(c2) << 32) | ((uint64_t)__half_as_ushort(d2) << 48);
}

__device__ __forceinline__ void ldsm4(uint32_t* r, uint32_t addr) {
    asm volatile("ldmatrix.sync.aligned.m8n8.x4.shared.b16 {%0,%1,%2,%3}, [%4];"
                 : "=r"(r[0]), "=r"(r[1]), "=r"(r[2]), "=r"(r[3]) : "r"(addr));
}

__device__ __forceinline__ void mma16816(float* c, const uint32_t* a, uint32_t b0, uint32_t b1) {
    asm volatile("mma.sync.aligned.m16n8k16.row.col.f32.f16.f16.f32 "
                 "{%0,%1,%2,%3}, {%4,%5,%6,%7}, {%8,%9}, {%0,%1,%2,%3};"
                 : "+f"(c[0]), "+f"(c[1]), "+f"(c[2]), "+f"(c[3])
                 : "r"(a[0]), "r"(a[1]), "r"(a[2]), "r"(a[3]), "r"(b0), "r"(b1));
}

// ---- prep: split embedding into [Eh1 | Eh2 | Eh1] rows (pitch 200) + norms ----
__global__ void vq_prep(const float* __restrict__ emb) {
    int gid = blockIdx.x * blockDim.x + threadIdx.x;
    if (gid >= KK * 16) return;
    int k = gid >> 4, s = gid & 15;                 // s: float4 segment (d = 4s..4s+3)
    float4 v = ((const float4*)emb)[gid];
    uint64_t p1, p2;
    pack_h12(v, p1, p2);
    __half* row = g_B + k * PITCH;
    *(uint64_t*)(row + s * 4)       = p1;           // k-halfs   0.. 63: Eh1
    *(uint64_t*)(row + 64 + s * 4)  = p2;           // k-halfs  64..127: Eh2
    *(uint64_t*)(row + 128 + s * 4) = p1;           // k-halfs 128..191: Eh1
    if (s == 0) {
        const float4* r = (const float4*)(emb + k * DD);
        float acc = 0.f;
        #pragma unroll
        for (int i = 0; i < 16; i++) {
            float4 e = r[i];
            acc += e.x * e.x + e.y * e.y + e.z * e.z + e.w * e.w;
        }
        g_sc[k] = 0.5f * acc;
    }
}

// ---- main: persistent HMMA GEMM + in-register argmin ----
__global__ __launch_bounds__(THREADS, 1)
void vq_hmma(const float* __restrict__ x,
             const float* __restrict__ emb,
             float* __restrict__ out,
             int N, int write_idx, int ntiles) {
    extern __shared__ char sm[];
    const uint32_t sb = smem_u32(sm);
    const int tid = threadIdx.x;
    const int wid = tid >> 5;
    const int lane = tid & 31;

    // Stage B (pre-split/padded) + norms once per CTA
    {
        const uint4* s4 = (const uint4*)g_B;
        uint4* d4 = (uint4*)(sm + SMB_B);
        #pragma unroll 4
        for (int i = tid; i < KK * PITCHB / 16; i += THREADS) d4[i] = s4[i];
        for (int i = tid; i < KK; i += THREADS)
            ((float*)(sm + SMB_SC))[i] = g_sc[i];
    }

    const int mw = wid >> 2, nw = wid & 3;
    const int m0 = mw * 16, n0 = nw * 128;
    // ldmatrix lane addresses (canonical x4 patterns)
    const uint32_t aaddr0 = sb + SMB_A
        + (uint32_t)(m0 + (lane & 15)) * PITCHB + ((lane >> 4) & 1) * 16;
    const uint32_t baddr0 = sb + SMB_B
        + (uint32_t)(n0 + (lane & 7) + ((lane >> 4) & 1) * 8) * PITCHB
        + ((lane >> 3) & 1) * 16;

    const int srow = tid >> 3;          // staging row (0..31)
    const int sseg = tid & 7;           // float4-pair segment (d = sseg*8)
    float* vals = (float*)(sm + SMB_VAL);
    int*   idxs = (int*)(sm + SMB_IDX);
    const float* scp = (const float*)(sm + SMB_SC);

    // Prefetch first tile (x row fragment) into registers
    float4 pa = make_float4(0, 0, 0, 0), pb = pa;
    {
        int g = blockIdx.x * TILE_M + srow;
        if (blockIdx.x < ntiles && g < N) {
            pa = ((const float4*)x)[(size_t)g * 16 + sseg * 2];
            pb = ((const float4*)x)[(size_t)g * 16 + sseg * 2 + 1];
        }
    }

    for (int tile = blockIdx.x; tile < ntiles; tile += gridDim.x) {
        // ---- store A tile: [h1 | h1 | h2] to match B's [Eh1 | Eh2 | Eh1] ----
        // dot = h1.Eh1 + h1.Eh2 + h2.Eh1  (h2.Eh2 term ~5e-7, negligible)
        {
            uint64_t a1, a2, b1, b2;
            pack_h12(pa, a1, a2);
            pack_h12(pb, b1, b2);
            char* arow = sm + SMB_A + srow * PITCHB + sseg * 16;
            *(uint64_t*)(arow)       = a1;  *(uint64_t*)(arow + 8)   = b1;  // k   0.. 63: h1
            *(uint64_t*)(arow + 128) = a1;  *(uint64_t*)(arow + 136) = b1;  // k  64..127: h1
            *(uint64_t*)(arow + 256) = a2;  *(uint64_t*)(arow + 264) = b2;  // k 128..191: h2
        }
        // ---- prefetch next tile early (overlaps with MMA) ----
        {
            int t2 = tile + gridDim.x;
            pa = make_float4(0, 0, 0, 0); pb = pa;
            if (t2 < ntiles) {
                int g = t2 * TILE_M + srow;
                if (g < N) {
                    pa = ((const float4*)x)[(size_t)g * 16 + sseg * 2];
                    pb = ((const float4*)x)[(size_t)g * 16 + sseg * 2 + 1];
                }
            }
        }
        __syncthreads();   // A (and B on first iter) visible

        // ---- GEMM: 16 n-tiles x 12 k-steps of m16n8k16 ----
        float c[16][4];
        #pragma unroll
        for (int i = 0; i < 16; i++) { c[i][0] = c[i][1] = c[i][2] = c[i][3] = 0.f; }

        #pragma unroll 1
        for (int ks = 0; ks < 12; ks++) {
            uint32_t a[4];
            ldsm4(a, aaddr0 + ks * 32);
            #pragma unroll
            for (int ntp = 0; ntp < 8; ntp++) {
                uint32_t b[4];
                ldsm4(b, baddr0 + ntp * (16 * PITCHB) + ks * 32);
                mma16816(c[2 * ntp],     a, b[0], b[1]);
                mma16816(c[2 * ntp + 1], a, b[2], b[3]);
            }
        }

        // ---- in-register argmin (maximize dot - 0.5||e||^2) ----
        float bvA = -3.402823466e38f, bvB = -3.402823466e38f;
        int biA = 0, biB = 0;
        #pragma unroll
        for (int nt = 0; nt < 16; nt++) {
            int col0 = n0 + nt * 8 + (lane & 3) * 2;
            float s0 = scp[col0], s1 = scp[col0 + 1];
            float v;
            v = c[nt][0] - s0; if (v > bvA) { bvA = v; biA = col0; }
            v = c[nt][1] - s1; if (v > bvA) { bvA = v; biA = col0 + 1; }
            v = c[nt][2] - s0; if (v > bvB) { bvB = v; biB = col0; }
            v = c[nt][3] - s1; if (v > bvB) { bvB = v; biB = col0 + 1; }
        }
        #pragma unroll
        for (int off = 1; off <= 2; off <<= 1) {
            float ov; int oi;
            ov = __shfl_xor_sync(0xffffffff, bvA, off);
            oi = __shfl_xor_sync(0xffffffff, biA, off);
            if (ov > bvA || (ov == bvA && oi < biA)) { bvA = ov; biA = oi; }
            ov = __shfl_xor_sync(0xffffffff, bvB, off);
            oi = __shfl_xor_sync(0xffffffff, biB, off);
            if (ov > bvB || (ov == bvB && oi < biB)) { bvB = ov; biB = oi; }
        }
        if ((lane & 3) == 0) {
            int rowA = m0 + (lane >> 2), rowB = rowA + 8;
            vals[rowA * 4 + nw] = bvA;  idxs[rowA * 4 + nw] = biA;
            vals[rowB * 4 + nw] = bvB;  idxs[rowB * 4 + nw] = biB;
        }
        __syncthreads();

        // ---- combine the 4 N-warps per row ----
        if (tid < TILE_M) {
            float v = vals[tid * 4];  int bi = idxs[tid * 4];
            #pragma unroll
            for (int w = 1; w < 4; w++) {
                float ov = vals[tid * 4 + w];  int oi = idxs[tid * 4 + w];
                if (ov > v || (ov == v && oi < bi)) { v = ov; bi = oi; }
            }
            idxs[tid * 4] = bi;
            if (write_idx) {
                int g = tile * TILE_M + tid;
                if (g < N) out[(size_t)N * DD + g] = (float)bi;
            }
        }
        __syncthreads();

        // ---- gather output rows from embedding (L2-resident) ----
        {
            int g = tile * TILE_M + srow;
            if (g < N) {
                int idx = idxs[srow * 4];
                float4 e0 = ((const float4*)emb)[(size_t)idx * 16 + sseg * 2];
                float4 e1 = ((const float4*)emb)[(size_t)idx * 16 + sseg * 2 + 1];
                ((float4*)out)[(size_t)g * 16 + sseg * 2]     = e0;
                ((float4*)out)[(size_t)g * 16 + sseg * 2 + 1] = e1;
            }
        }
        // next iteration's first __syncthreads orders A/val/idx reuse
    }
}

extern "C" void kernel_launch(void* const* d_in, const int* in_sizes, int n_in,
                              void* d_out, int out_size) {
    const float* x   = (const float*)d_in[0];   // flat_x  [N, 64]
    const float* emb = (const float*)d_in[1];   // codes   [512, 64]
    float* out = (float*)d_out;

    const int N = in_sizes[0] / DD;
    const int write_idx = (out_size >= N * DD + N) ? 1 : 0;
    const int ntiles = (N + TILE_M - 1) / TILE_M;

    vq_prep<<<32, 256>>>(emb);

    cudaFuncSetAttribute(vq_hmma,
                         cudaFuncAttributeMaxDynamicSharedMemorySize, SMB_TOT);
    vq_hmma<<<148, THREADS, SMB_TOT>>>(x, emb, out, N, write_idx, ntiles);
}

// round 8
// speedup vs baseline: 3.4049x; 1.2013x over previous
#include <cuda_runtime.h>
#include <cuda_fp16.h>
#include <cstdint>

#define DD 64
#define KK 512
#define TILE_M 64
#define THREADS 256
#define PITCH 136          // halfs per row: [h1(64) | h2(64) | pad(8)]
#define PITCHB 272         // bytes per row (68 words ≡ 4 mod 32 -> ldmatrix conflict-free)

// smem layout (byte offsets)
#define SMB_B    0                       // 512 * 272 = 139264
#define SMB_A    139264                  // 64 * 272  = 17408
#define SMB_SC   156672                  // 512 floats = 2048
#define SMB_VAL  158720                  // float vals[64][4] = 1024
#define SMB_IDX  159744                  // int   idxs[64][4] = 1024
#define SMB_TOT  160768

__device__ __align__(16) __half g_B[KK * PITCH];
__device__ float g_sc[KK];

__device__ __forceinline__ uint32_t smem_u32(const void* p) {
    uint32_t a;
    asm("{ .reg .u64 t; cvta.to.shared.u64 t, %1; cvt.u32.u64 %0, t; }" : "=r"(a) : "l"(p));
    return a;
}

// split float4 -> fp16 hi (p1) and fp16 residual (p2)
__device__ __forceinline__ void pack_h12(float4 v, uint64_t& p1, uint64_t& p2) {
    __half a1 = __float2half_rn(v.x), b1 = __float2half_rn(v.y);
    __half c1 = __float2half_rn(v.z), d1 = __float2half_rn(v.w);
    __half a2 = __float2half_rn(v.x - __half2float(a1));
    __half b2 = __float2half_rn(v.y - __half2float(b1));
    __half c2 = __float2half_rn(v.z - __half2float(c1));
    __half d2 = __float2half_rn(v.w - __half2float(d1));
    p1 = (uint64_t)__half_as_ushort(a1) | ((uint64_t)__half_as_ushort(b1) << 16)
       | ((uint64_t)__half_as_ushort(c1) << 32) | ((uint64_t)__half_as_ushort(d1) << 48);
    p2 = (uint64_t)__half_as_ushort(a2) | ((uint64_t)__half_as_ushort(b2) << 16)
       | ((uint64_t)__half_as_ushort(c2) << 32) | ((uint64_t)__half_as_ushort(d2) << 48);
}

__device__ __forceinline__ void ldsm4(uint32_t* r, uint32_t addr) {
    asm volatile("ldmatrix.sync.aligned.m8n8.x4.shared.b16 {%0,%1,%2,%3}, [%4];"
                 : "=r"(r[0]), "=r"(r[1]), "=r"(r[2]), "=r"(r[3]) : "r"(addr));
}

__device__ __forceinline__ void mma16816(float* c, const uint32_t* a, uint32_t b0, uint32_t b1) {
    asm volatile("mma.sync.aligned.m16n8k16.row.col.f32.f16.f16.f32 "
                 "{%0,%1,%2,%3}, {%4,%5,%6,%7}, {%8,%9}, {%0,%1,%2,%3};"
                 : "+f"(c[0]), "+f"(c[1]), "+f"(c[2]), "+f"(c[3])
                 : "r"(a[0]), "r"(a[1]), "r"(a[2]), "r"(a[3]), "r"(b0), "r"(b1));
}

// ---- prep: split embedding rows into [Eh1 | Eh2] (pitch 136) + norms ----
__global__ void vq_prep(const float* __restrict__ emb) {
    int gid = blockIdx.x * blockDim.x + threadIdx.x;
    if (gid >= KK * 16) return;
    int k = gid >> 4, s = gid & 15;
    float4 v = ((const float4*)emb)[gid];
    uint64_t p1, p2;
    pack_h12(v, p1, p2);
    __half* row = g_B + k * PITCH;
    *(uint64_t*)(row + s * 4)      = p1;    // halfs  0..63 : Eh1
    *(uint64_t*)(row + 64 + s * 4) = p2;    // halfs 64..127: Eh2
    if (s == 0) {
        const float4* r = (const float4*)(emb + k * DD);
        float acc = 0.f;
        #pragma unroll
        for (int i = 0; i < 16; i++) {
            float4 e = r[i];
            acc += e.x * e.x + e.y * e.y + e.z * e.z + e.w * e.w;
        }
        g_sc[k] = 0.5f * acc;
    }
}

// ---- main: persistent HMMA GEMM + in-register argmin ----
__global__ __launch_bounds__(THREADS, 1)
void vq_hmma(const float* __restrict__ x,
             const float* __restrict__ emb,
             float* __restrict__ out,
             int N, int write_idx, int ntiles) {
    extern __shared__ char sm[];
    const uint32_t sb = smem_u32(sm);
    const int tid = threadIdx.x;
    const int wid = tid >> 5;
    const int lane = tid & 31;

    // Stage B + norms once per CTA
    {
        const uint4* s4 = (const uint4*)g_B;
        uint4* d4 = (uint4*)(sm + SMB_B);
        #pragma unroll 4
        for (int i = tid; i < KK * PITCHB / 16; i += THREADS) d4[i] = s4[i];
        for (int i = tid; i < KK; i += THREADS)
            ((float*)(sm + SMB_SC))[i] = g_sc[i];
    }

    const int mw = wid >> 2, nw = wid & 3;
    const int m0 = mw * 32, n0 = nw * 128;
    uint32_t aaddr[2];
    #pragma unroll
    for (int sub = 0; sub < 2; sub++)
        aaddr[sub] = sb + SMB_A + (uint32_t)(m0 + sub * 16 + (lane & 15)) * PITCHB
                   + ((lane >> 4) & 1) * 16;
    const uint32_t baddr = sb + SMB_B
        + (uint32_t)(n0 + (lane & 7) + ((lane >> 4) & 1) * 8) * PITCHB
        + ((lane >> 3) & 1) * 16;

    const int srow = tid >> 3;          // staging row base (0..31), +32 for j=1
    const int sseg = tid & 7;           // float4-pair segment
    float* vals = (float*)(sm + SMB_VAL);
    int*   idxs = (int*)(sm + SMB_IDX);
    const float* scp = (const float*)(sm + SMB_SC);

    // Prefetch first tile
    float4 pa[2], pb[2];
    #pragma unroll
    for (int j = 0; j < 2; j++) { pa[j] = make_float4(0,0,0,0); pb[j] = pa[j]; }
    if (blockIdx.x < ntiles) {
        #pragma unroll
        for (int j = 0; j < 2; j++) {
            int g = blockIdx.x * TILE_M + srow + j * 32;
            if (g < N) {
                pa[j] = ((const float4*)x)[(size_t)g * 16 + sseg * 2];
                pb[j] = ((const float4*)x)[(size_t)g * 16 + sseg * 2 + 1];
            }
        }
    }

    for (int tile = blockIdx.x; tile < ntiles; tile += gridDim.x) {
        // ---- store A tile: [h1 | h2], pitch 272B ----
        #pragma unroll
        for (int j = 0; j < 2; j++) {
            uint64_t a1, a2, b1, b2;
            pack_h12(pa[j], a1, a2);
            pack_h12(pb[j], b1, b2);
            char* arow = sm + SMB_A + (srow + j * 32) * PITCHB + sseg * 16;
            *(uint64_t*)(arow)       = a1;  *(uint64_t*)(arow + 8)   = b1;  // h1
            *(uint64_t*)(arow + 128) = a2;  *(uint64_t*)(arow + 136) = b2;  // h2
        }
        // ---- prefetch next tile (overlaps GEMM) ----
        {
            int t2 = tile + gridDim.x;
            #pragma unroll
            for (int j = 0; j < 2; j++) { pa[j] = make_float4(0,0,0,0); pb[j] = pa[j]; }
            if (t2 < ntiles) {
                #pragma unroll
                for (int j = 0; j < 2; j++) {
                    int g = t2 * TILE_M + srow + j * 32;
                    if (g < N) {
                        pa[j] = ((const float4*)x)[(size_t)g * 16 + sseg * 2];
                        pb[j] = ((const float4*)x)[(size_t)g * 16 + sseg * 2 + 1];
                    }
                }
            }
        }
        __syncthreads();   // A visible (B visible since prologue)

        // ---- load A fragments once: 2 subtiles x 4 ksteps x (h1,h2) ----
        uint32_t ah1[2][4][4], ah2[2][4][4];
        #pragma unroll
        for (int sub = 0; sub < 2; sub++)
            #pragma unroll
            for (int s = 0; s < 4; s++) {
                ldsm4(ah1[sub][s], aaddr[sub] + s * 32);
                ldsm4(ah2[sub][s], aaddr[sub] + 128 + s * 32);
            }

        // running bests: [sub][rowA/rowB]
        float bv[2][2] = {{-3.402823466e38f, -3.402823466e38f},
                          {-3.402823466e38f, -3.402823466e38f}};
        int   bi[2][2] = {{0, 0}, {0, 0}};

        // ---- per n-pair (16 cols): load 8 B frags, 48 MMAs, argmin ----
        #pragma unroll 1
        for (int np = 0; np < 8; np++) {
            const uint32_t bb = baddr + np * (16 * PITCHB);
            uint32_t b1f[4][4], b2f[4][4];
            #pragma unroll
            for (int s = 0; s < 4; s++) ldsm4(b1f[s], bb + s * 32);        // Eh1
            #pragma unroll
            for (int s = 0; s < 4; s++) ldsm4(b2f[s], bb + 128 + s * 32);  // Eh2

            float c[2][2][4];
            #pragma unroll
            for (int sub = 0; sub < 2; sub++)
                #pragma unroll
                for (int t = 0; t < 2; t++)
                    c[sub][t][0] = c[sub][t][1] = c[sub][t][2] = c[sub][t][3] = 0.f;

            #pragma unroll
            for (int s = 0; s < 4; s++)
                #pragma unroll
                for (int sub = 0; sub < 2; sub++) {
                    mma16816(c[sub][0], ah1[sub][s], b1f[s][0], b1f[s][1]);  // h1.Eh1
                    mma16816(c[sub][1], ah1[sub][s], b1f[s][2], b1f[s][3]);
                }
            #pragma unroll
            for (int s = 0; s < 4; s++)
                #pragma unroll
                for (int sub = 0; sub < 2; sub++) {
                    mma16816(c[sub][0], ah1[sub][s], b2f[s][0], b2f[s][1]);  // h1.Eh2
                    mma16816(c[sub][1], ah1[sub][s], b2f[s][2], b2f[s][3]);
                }
            #pragma unroll
            for (int s = 0; s < 4; s++)
                #pragma unroll
                for (int sub = 0; sub < 2; sub++) {
                    mma16816(c[sub][0], ah2[sub][s], b1f[s][0], b1f[s][1]);  // h2.Eh1
                    mma16816(c[sub][1], ah2[sub][s], b1f[s][2], b1f[s][3]);
                }

            const int col0 = n0 + np * 16 + (lane & 3) * 2;
            const float s0 = scp[col0],     s1 = scp[col0 + 1];
            const float s2 = scp[col0 + 8], s3 = scp[col0 + 9];
            #pragma unroll
            for (int sub = 0; sub < 2; sub++) {
                float v;
                v = c[sub][0][0] - s0; if (v > bv[sub][0]) { bv[sub][0] = v; bi[sub][0] = col0; }
                v = c[sub][0][1] - s1; if (v > bv[sub][0]) { bv[sub][0] = v; bi[sub][0] = col0 + 1; }
                v = c[sub][1][0] - s2; if (v > bv[sub][0]) { bv[sub][0] = v; bi[sub][0] = col0 + 8; }
                v = c[sub][1][1] - s3; if (v > bv[sub][0]) { bv[sub][0] = v; bi[sub][0] = col0 + 9; }
                v = c[sub][0][2] - s0; if (v > bv[sub][1]) { bv[sub][1] = v; bi[sub][1] = col0; }
                v = c[sub][0][3] - s1; if (v > bv[sub][1]) { bv[sub][1] = v; bi[sub][1] = col0 + 1; }
                v = c[sub][1][2] - s2; if (v > bv[sub][1]) { bv[sub][1] = v; bi[sub][1] = col0 + 8; }
                v = c[sub][1][3] - s3; if (v > bv[sub][1]) { bv[sub][1] = v; bi[sub][1] = col0 + 9; }
            }
        }

        // ---- reduce across the 4 lanes sharing a row, write per-warp bests ----
        #pragma unroll
        for (int sub = 0; sub < 2; sub++)
            #pragma unroll
            for (int r = 0; r < 2; r++) {
                #pragma unroll
                for (int off = 1; off <= 2; off <<= 1) {
                    float ov = __shfl_xor_sync(0xffffffff, bv[sub][r], off);
                    int   oi = __shfl_xor_sync(0xffffffff, bi[sub][r], off);
                    if (ov > bv[sub][r] || (ov == bv[sub][r] && oi < bi[sub][r])) {
                        bv[sub][r] = ov; bi[sub][r] = oi;
                    }
                }
                if ((lane & 3) == 0) {
                    int row = m0 + sub * 16 + r * 8 + (lane >> 2);
                    vals[row * 4 + nw] = bv[sub][r];
                    idxs[row * 4 + nw] = bi[sub][r];
                }
            }
        __syncthreads();

        // ---- combine 4 N-warps per row ----
        if (tid < TILE_M) {
            float v = vals[tid * 4];  int b = idxs[tid * 4];
            #pragma unroll
            for (int w = 1; w < 4; w++) {
                float ov = vals[tid * 4 + w];  int oi = idxs[tid * 4 + w];
                if (ov > v || (ov == v && oi < b)) { v = ov; b = oi; }
            }
            idxs[tid * 4] = b;
            if (write_idx) {
                int g = tile * TILE_M + tid;
                if (g < N) out[(size_t)N * DD + g] = (float)b;
            }
        }
        __syncthreads();

        // ---- gather output rows from embedding (L2-resident) ----
        {
            int row = tid >> 2;
            int g = tile * TILE_M + row;
            if (g < N) {
                int idx = idxs[row * 4];
                #pragma unroll
                for (int j = 0; j < 4; j++) {
                    int seg = (tid & 3) + j * 4;
                    ((float4*)out)[(size_t)g * 16 + seg] =
                        ((const float4*)emb)[(size_t)idx * 16 + seg];
                }
            }
        }
    }
}

extern "C" void kernel_launch(void* const* d_in, const int* in_sizes, int n_in,
                              void* d_out, int out_size) {
    const float* x   = (const float*)d_in[0];   // flat_x  [N, 64]
    const float* emb = (const float*)d_in[1];   // codes   [512, 64]
    float* out = (float*)d_out;

    const int N = in_sizes[0] / DD;
    const int write_idx = (out_size >= N * DD + N) ? 1 : 0;
    const int ntiles = (N + TILE_M - 1) / TILE_M;

    vq_prep<<<32, 256>>>(emb);

    cudaFuncSetAttribute(vq_hmma,
                         cudaFuncAttributeMaxDynamicSharedMemorySize, SMB_TOT);
    vq_hmma<<<148, THREADS, SMB_TOT>>>(x, emb, out, N, write_idx, ntiles);
}